// round 10
// baseline (speedup 1.0000x reference)
#include <cuda_runtime.h>

#define HID 24
#define TPB 128
#define NCONST 948   // 864 weights + 48 cRZ + 24 cN + 12 cNH (u64 entries)

typedef unsigned long long u64;

__device__ __align__(16) static u64 g_all[NCONST];   // staging (written by pack kernel)
__constant__ __align__(16) u64 cAll[NCONST];         // weights via constant port (LDC)

__device__ __forceinline__ u64 pack2(float x, float y) {
    u64 r; asm("mov.b64 %0, {%1, %2};" : "=l"(r) : "f"(x), "f"(y)); return r;
}
__device__ __forceinline__ void unpack2(u64 v, float &x, float &y) {
    asm("mov.b64 {%0, %1}, %2;" : "=f"(x), "=f"(y) : "l"(v));
}
__device__ __forceinline__ u64 ffma2(u64 a, u64 b, u64 c) {
    u64 d; asm("fma.rn.f32x2 %0, %1, %2, %3;" : "=l"(d) : "l"(a), "l"(b), "l"(c)); return d;
}
__device__ __forceinline__ u64 fadd2(u64 a, u64 b) {
    u64 d; asm("add.rn.f32x2 %0, %1, %2;" : "=l"(d) : "l"(a), "l"(b)); return d;
}
__device__ __forceinline__ float ex2a(float x) {
    float r; asm("ex2.approx.f32 %0, %1;" : "=f"(r) : "f"(x)); return r;
}
__device__ __forceinline__ float rcpa(float x) {
    float r; asm("rcp.approx.f32 %0, %1;" : "=f"(r) : "f"(x)); return r;
}
__device__ __forceinline__ float sig_f(float v) {
    return rcpa(1.0f + ex2a(v * -1.442695041f));
}
__device__ __forceinline__ float tanh_f(float v) {
    return fmaf(2.0f, rcpa(1.0f + ex2a(v * -2.885390082f)), -1.0f);
}

// Layout of g_all/cAll (u64 index):
//  [0,864)   weights: e = (((qq*6+c)*9+j)*2+u)*2+half ->
//            pack2(W_hh[r0][k], W_hh[r0+1][k]), r0=(j/3)*24+6qq+2(j%3), k=4c+2u+half
//  [864,912) cRZ[qq][j6] ulonglong2: .x=(W_ih pair) .y=(b_ih+b_hh pair), r0=(j6/3)*24+6qq+2(j6%3)
//  [912,936) cN[qq][p]  ulonglong2: .x=(W_ih_n pair) .y=(b_ih_n pair), r0=48+6qq+2p
//  [936,948) cNH[qq*3+p]: b_hh n pair
__global__ void pack_weights(const float* __restrict__ W_ih,
                             const float* __restrict__ b_ih,
                             const float* __restrict__ W_hh,
                             const float* __restrict__ b_hh)
{
    int e = blockIdx.x * blockDim.x + threadIdx.x;
    if (e >= NCONST) return;
    if (e < 864) {
        int half = e & 1, v = e >> 1;
        int u = v & 1, v2 = v >> 1;
        int j = v2 % 9, v3 = v2 / 9;
        int c = v3 % 6, qq = v3 / 6;
        int gate = j / 3, p = j % 3;
        int r0 = gate * 24 + 6 * qq + 2 * p;
        int k  = 4 * c + 2 * u + half;
        g_all[e] = pack2(W_hh[r0 * HID + k], W_hh[(r0 + 1) * HID + k]);
    } else if (e < 912) {
        int v = e - 864;
        int part = v & 1, pi = v >> 1;     // pi = qq*6 + j6
        int qq = pi / 6, j6 = pi % 6;
        int gate = j6 / 3, p = j6 % 3;
        int r0 = gate * 24 + 6 * qq + 2 * p;
        g_all[e] = part == 0
            ? pack2(W_ih[r0], W_ih[r0 + 1])
            : pack2(b_ih[r0] + b_hh[r0], b_ih[r0 + 1] + b_hh[r0 + 1]);
    } else if (e < 936) {
        int v = e - 912;
        int part = v & 1, pi = v >> 1;     // pi = qq*3 + p
        int qq = pi / 3, p = pi % 3;
        int r0 = 48 + 6 * qq + 2 * p;
        g_all[e] = part == 0
            ? pack2(W_ih[r0], W_ih[r0 + 1])
            : pack2(b_ih[r0], b_ih[r0 + 1]);
    } else {
        int pi = e - 936;                  // qq*3 + p
        int qq = pi / 3, p = pi % 3;
        int r0 = 48 + 6 * qq + 2 * p;
        g_all[e] = pack2(b_hh[r0], b_hh[r0 + 1]);
    }
}

// CTA: 4 warps = 4 gate-quarters; warp q owns gate rows {r,z,n}x[6q,6q+6) and
// hidden units 6q..6q+5. Lane m carries seqs (cta*64 + 2m, +1).
// All weights come from the CONSTANT port (LDC) — zero L1 crossbar traffic.
__global__ void __launch_bounds__(TPB, 4)
trendgru_kernel(const float* __restrict__ x,
                const float* __restrict__ fc_w,
                const float* __restrict__ fc_b,
                float* __restrict__ out,
                int B, int T)
{
    __shared__ __align__(16) ulonglong2 hbw[3][12][32];  // h ring: [buf][pair][lane]{A,B}
    __shared__ float fcs[4][32][2][2];                   // fc partials [q][m][s][o]

    const int tid = threadIdx.x;
    const int q   = tid >> 5;
    const int m   = tid & 31;

    // zero h ring buffer 0 (t=0 reads it)
    for (int i = tid; i < 12 * 32; i += TPB)
        hbw[0][i >> 5][i & 31] = make_ulonglong2(0ULL, 0ULL);
    __syncthreads();

    const ulonglong2* wq  = reinterpret_cast<const ulonglong2*>(cAll) + q * 108;
    const ulonglong2* cRZ = reinterpret_cast<const ulonglong2*>(cAll + 864) + q * 6;
    const ulonglong2* cN  = reinterpret_cast<const ulonglong2*>(cAll + 912) + q * 3;
    const u64*        cNH = cAll + 936 + q * 3;

    const int sA = blockIdx.x * 64 + 2 * m;
    const float* xrA = x + (size_t)sA * T;
    const float* xrB = xrA + T;

    const u64 SGN2 = 0x8000000080000000ULL;

    float xA = __ldg(xrA);
    float xB = __ldg(xrB);
    int rb = 0, wb = 1;

    for (int t = 0; t < T; t++) {
        const int tn = (t + 1 < T) ? (t + 1) : t;
        const float xAn = __ldg(xrA + tn);
        const float xBn = __ldg(xrB + tn);

        const u64 x2A = pack2(xA, xA);
        const u64 x2B = pack2(xB, xB);

        u64 acc[2][9], xn[2][3];
        #pragma unroll
        for (int j6 = 0; j6 < 6; j6++) {
            const ulonglong2 w = cRZ[j6];
            acc[0][j6] = ffma2(w.x, x2A, w.y);
            acc[1][j6] = ffma2(w.x, x2B, w.y);
        }
        #pragma unroll
        for (int p = 0; p < 3; p++) {
            const ulonglong2 wn = cN[p];
            xn[0][p] = ffma2(wn.x, x2A, wn.y);
            xn[1][p] = ffma2(wn.x, x2B, wn.y);
            const u64 bv = cNH[p];
            acc[0][6 + p] = bv;
            acc[1][6 + p] = bv;
        }

        // matvec: 6 k-chunks of 4 scalars; weights via constant port
        #pragma unroll
        for (int c = 0; c < 6; c++) {
            const ulonglong2 ha = hbw[rb][2 * c][m];      // pair 2c  {A,B}
            const ulonglong2 hb = hbw[rb][2 * c + 1][m];  // pair 2c+1{A,B}
            float A0, A1, A2, A3, B0, B1, B2, B3;
            unpack2(ha.x, A0, A1); unpack2(hb.x, A2, A3);
            unpack2(ha.y, B0, B1); unpack2(hb.y, B2, B3);
            const u64 eA0 = pack2(A0, A0), eA1 = pack2(A1, A1);
            const u64 eA2 = pack2(A2, A2), eA3 = pack2(A3, A3);
            const u64 eB0 = pack2(B0, B0), eB1 = pack2(B1, B1);
            const u64 eB2 = pack2(B2, B2), eB3 = pack2(B3, B3);
            #pragma unroll
            for (int j = 0; j < 9; j++) {
                const ulonglong2 w0 = wq[(c * 9 + j) * 2];      // k = 4c, 4c+1
                const ulonglong2 w1 = wq[(c * 9 + j) * 2 + 1];  // k = 4c+2, 4c+3
                acc[0][j] = ffma2(w0.x, eA0, acc[0][j]);
                acc[0][j] = ffma2(w0.y, eA1, acc[0][j]);
                acc[0][j] = ffma2(w1.x, eA2, acc[0][j]);
                acc[0][j] = ffma2(w1.y, eA3, acc[0][j]);
                acc[1][j] = ffma2(w0.x, eB0, acc[1][j]);
                acc[1][j] = ffma2(w0.y, eB1, acc[1][j]);
                acc[1][j] = ffma2(w1.x, eB2, acc[1][j]);
                acc[1][j] = ffma2(w1.y, eB3, acc[1][j]);
            }
        }

        // gates + h update for own 3 pairs, both seqs
        #pragma unroll
        for (int p = 0; p < 3; p++) {
            const ulonglong2 hold = hbw[rb][3 * q + p][m];
            u64 hnew[2];
            #pragma unroll
            for (int s = 0; s < 2; s++) {
                float a0, a1, c0, c1;
                unpack2(acc[s][p], a0, a1);
                unpack2(acc[s][3 + p], c0, c1);
                const u64 r2 = pack2(sig_f(a0), sig_f(a1));
                const u64 z2 = pack2(sig_f(c0), sig_f(c1));
                const u64 npre = ffma2(r2, acc[s][6 + p], xn[s][p]);
                float n0, n1; unpack2(npre, n0, n1);
                const u64 n2 = pack2(tanh_f(n0), tanh_f(n1));
                const u64 hp = (s == 0) ? hold.x : hold.y;
                hnew[s] = ffma2(z2, fadd2(hp, n2 ^ SGN2), n2);
            }
            hbw[wb][3 * q + p][m] = make_ulonglong2(hnew[0], hnew[1]);
        }

        __syncthreads();
        xA = xAn;
        xB = xBn;
        rb = wb;
        wb = (wb == 2) ? 0 : (wb + 1);
    }

    // final fc: partials over own 6 units, combine across warps via SMEM
    float p0A = 0.f, p1A = 0.f, p0B = 0.f, p1B = 0.f;
    #pragma unroll
    for (int p = 0; p < 3; p++) {
        const int k = 6 * q + 2 * p;
        const float w00 = __ldg(fc_w + k),      w01 = __ldg(fc_w + k + 1);
        const float w10 = __ldg(fc_w + 24 + k), w11 = __ldg(fc_w + 24 + k + 1);
        const ulonglong2 hold = hbw[rb][3 * q + p][m];
        float e0, e1;
        unpack2(hold.x, e0, e1);
        p0A += w00 * e0 + w01 * e1;
        p1A += w10 * e0 + w11 * e1;
        unpack2(hold.y, e0, e1);
        p0B += w00 * e0 + w01 * e1;
        p1B += w10 * e0 + w11 * e1;
    }
    fcs[q][m][0][0] = p0A;
    fcs[q][m][0][1] = p1A;
    fcs[q][m][1][0] = p0B;
    fcs[q][m][1][1] = p1B;
    __syncthreads();

    if (q == 0) {
        const float fb0 = __ldg(fc_b + 0), fb1 = __ldg(fc_b + 1);
        float o0A = fb0, o1A = fb1, o0B = fb0, o1B = fb1;
        #pragma unroll
        for (int qq = 0; qq < 4; qq++) {
            o0A += fcs[qq][m][0][0];
            o1A += fcs[qq][m][0][1];
            o0B += fcs[qq][m][1][0];
            o1B += fcs[qq][m][1][1];
        }
        out[2 * sA + 0] = o0A;
        out[2 * sA + 1] = o1A;
        out[2 * sA + 2] = o0B;
        out[2 * sA + 3] = o1B;
    }
}

extern "C" void kernel_launch(void* const* d_in, const int* in_sizes, int n_in,
                              void* d_out, int out_size)
{
    const float* x    = (const float*)d_in[0];
    const float* W_ih = (const float*)d_in[1];
    const float* b_ih = (const float*)d_in[2];
    const float* W_hh = (const float*)d_in[3];
    const float* b_hh = (const float*)d_in[4];
    const float* fc_w = (const float*)d_in[5];
    const float* fc_b = (const float*)d_in[6];
    float* out = (float*)d_out;

    const int B = out_size / 2;
    const int T = in_sizes[0] / B;

    pack_weights<<<4, 256>>>(W_ih, b_ih, W_hh, b_hh);

    void* src = nullptr;
    cudaGetSymbolAddress(&src, g_all);
    cudaMemcpyToSymbolAsync(cAll, src, NCONST * sizeof(u64), 0,
                            cudaMemcpyDeviceToDevice, 0);

    const int grid = B / 64;   // 64 seqs per CTA
    trendgru_kernel<<<grid, TPB>>>(x, fc_w, fc_b, out, B, T);
}

// round 11
// speedup vs baseline: 2.8176x; 2.8176x over previous
#include <cuda_runtime.h>

#define HID 24
#define TPB 32
#define WSTRIDE 218   // u64 stride per q-block (216 payload + 2 pad): q*1744B mod 128 = {0,80,32,112} -> conflict-free

typedef unsigned long long u64;

__device__ __forceinline__ u64 pack2(float x, float y) {
    u64 r; asm("mov.b64 %0, {%1, %2};" : "=l"(r) : "f"(x), "f"(y)); return r;
}
__device__ __forceinline__ void unpack2(u64 v, float &x, float &y) {
    asm("mov.b64 {%0, %1}, %2;" : "=f"(x), "=f"(y) : "l"(v));
}
__device__ __forceinline__ u64 ffma2(u64 a, u64 b, u64 c) {
    u64 d; asm("fma.rn.f32x2 %0, %1, %2, %3;" : "=l"(d) : "l"(a), "l"(b), "l"(c)); return d;
}
__device__ __forceinline__ u64 fadd2(u64 a, u64 b) {
    u64 d; asm("add.rn.f32x2 %0, %1, %2;" : "=l"(d) : "l"(a), "l"(b)); return d;
}
__device__ __forceinline__ float ex2a(float x) {
    float r; asm("ex2.approx.f32 %0, %1;" : "=f"(r) : "f"(x)); return r;
}
__device__ __forceinline__ float rcpa(float x) {
    float r; asm("rcp.approx.f32 %0, %1;" : "=f"(r) : "f"(x)); return r;
}
__device__ __forceinline__ float sig_f(float v) {
    return rcpa(1.0f + ex2a(v * -1.442695041f));
}
__device__ __forceinline__ float tanh_f(float v) {
    return fmaf(2.0f, rcpa(1.0f + ex2a(v * -2.885390082f)), -1.0f);
}

// Cohort = 4 lanes <-> 4 sequences. Lane q owns gate rows {r,z,n} x units
// [6q, 6q+6) and computes FULL k=24 matvec for all 4 cohort seqs (no k-split,
// no reduce). h gathered lazily per k-pair via shfl from the owning lane.
__global__ void __launch_bounds__(TPB, 8)
trendgru_kernel(const float* __restrict__ x,
                const float* __restrict__ W_ih,
                const float* __restrict__ b_ih,
                const float* __restrict__ W_hh,
                const float* __restrict__ b_hh,
                const float* __restrict__ fc_w,
                const float* __restrict__ fc_b,
                float* __restrict__ out,
                int B, int T)
{
    // sW[q*218 + j*24 + k] = pack2(W_hh[r0][k], W_hh[r0+1][k]),
    //  j = gate*3+p (gate 0=r,1=z,2=n), r0 = gate*24 + 6q + 2p, k = 0..23
    __shared__ __align__(16) u64 sW[4 * WSTRIDE];
    __shared__ __align__(16) ulonglong2 cRZ[4][6];  // (W_ih pair, b_ih+b_hh pair)
    __shared__ __align__(16) ulonglong2 cN[4][3];   // (W_ih_n pair, b_ih_n pair)
    __shared__ u64 cNH[4][3];                       // b_hh n pairs

    const int tid = threadIdx.x;
    for (int i = tid; i < 4 * 216; i += TPB) {
        int qq = i / 216, rem = i % 216;
        int j = rem / 24, k = rem % 24;
        int gate = j / 3, p = j % 3;
        int r0 = gate * 24 + 6 * qq + 2 * p;
        sW[qq * WSTRIDE + j * 24 + k] = pack2(W_hh[r0 * HID + k], W_hh[(r0 + 1) * HID + k]);
    }
    if (tid < 24) {
        int qq = tid / 6, j6 = tid % 6;
        int gate = j6 / 3, p = j6 % 3;
        int r0 = gate * 24 + 6 * qq + 2 * p;
        cRZ[qq][j6].x = pack2(W_ih[r0], W_ih[r0 + 1]);
        cRZ[qq][j6].y = pack2(b_ih[r0] + b_hh[r0], b_ih[r0 + 1] + b_hh[r0 + 1]);
    }
    if (tid < 12) {
        int qq = tid / 3, p = tid % 3;
        int r0 = 48 + 6 * qq + 2 * p;
        cN[qq][p].x = pack2(W_ih[r0], W_ih[r0 + 1]);
        cN[qq][p].y = pack2(b_ih[r0], b_ih[r0 + 1]);
        cNH[qq][p]  = pack2(b_hh[r0], b_hh[r0 + 1]);
    }
    __syncthreads();

    const int q    = tid & 3;
    const int cbase = tid & ~3;                    // cohort base lane
    const int sbase = (blockIdx.x * TPB + tid) >> 2 << 2;  // 4 seqs per cohort

    const ulonglong2* wq = reinterpret_cast<const ulonglong2*>(&sW[q * WSTRIDE]);
    const float* xb = x + (size_t)sbase * T;

    u64 hown[4][3];   // own h pairs (units 6q..6q+5) for seqs sbase..sbase+3
    #pragma unroll
    for (int m = 0; m < 4; m++)
        #pragma unroll
        for (int p = 0; p < 3; p++) hown[m][p] = 0ULL;

    const u64 SGN2 = 0x8000000080000000ULL;

    float xv[4];
    #pragma unroll
    for (int m = 0; m < 4; m++) xv[m] = __ldg(xb + (size_t)m * T);

    for (int t = 0; t < T; t++) {
        const int tn = (t + 1 < T) ? (t + 1) : t;
        float xnx[4];
        #pragma unroll
        for (int m = 0; m < 4; m++) xnx[m] = __ldg(xb + (size_t)m * T + tn);

        u64 x2[4];
        #pragma unroll
        for (int m = 0; m < 4; m++) x2[m] = pack2(xv[m], xv[m]);

        u64 acc[4][9];
        #pragma unroll
        for (int j6 = 0; j6 < 6; j6++) {          // r (0-2), z (3-5): fold x-proj + biases
            const ulonglong2 w = cRZ[q][j6];
            #pragma unroll
            for (int m = 0; m < 4; m++)
                acc[m][j6] = ffma2(w.x, x2[m], w.y);
        }
        #pragma unroll
        for (int p = 0; p < 3; p++) {             // hn: start from b_hh
            const u64 bv = cNH[q][p];
            #pragma unroll
            for (int m = 0; m < 4; m++) acc[m][6 + p] = bv;
        }

        // matvec over 12 global h-pairs; pair i owned by lane cbase + i/3
        #pragma unroll
        for (int i = 0; i < 12; i++) {
            const int src = cbase + (i / 3);
            u64 e0[4], e1[4];
            #pragma unroll
            for (int m = 0; m < 4; m++) {
                const u64 hv = __shfl_sync(0xFFFFFFFFu, hown[m][i % 3], src);
                float h0, h1; unpack2(hv, h0, h1);
                e0[m] = pack2(h0, h0);
                e1[m] = pack2(h1, h1);
            }
            #pragma unroll
            for (int j = 0; j < 9; j++) {
                const ulonglong2 w = wq[j * 12 + i];   // k = 2i (x), 2i+1 (y)
                #pragma unroll
                for (int m = 0; m < 4; m++) {
                    acc[m][j] = ffma2(w.x, e0[m], acc[m][j]);
                    acc[m][j] = ffma2(w.y, e1[m], acc[m][j]);
                }
            }
        }

        // gates + h update: own 3 pairs x 4 seqs
        #pragma unroll
        for (int m = 0; m < 4; m++) {
            #pragma unroll
            for (int p = 0; p < 3; p++) {
                float a0, a1, c0, c1;
                unpack2(acc[m][p], a0, a1);
                unpack2(acc[m][3 + p], c0, c1);
                const u64 r2 = pack2(sig_f(a0), sig_f(a1));
                const u64 z2 = pack2(sig_f(c0), sig_f(c1));
                const ulonglong2 wn = cN[q][p];
                const u64 xn = ffma2(wn.x, x2[m], wn.y);
                const u64 npre = ffma2(r2, acc[m][6 + p], xn);
                float n0, n1; unpack2(npre, n0, n1);
                const u64 n2 = pack2(tanh_f(n0), tanh_f(n1));
                // h = n + z*(h - n)
                hown[m][p] = ffma2(z2, fadd2(hown[m][p], n2 ^ SGN2), n2);
            }
        }

        #pragma unroll
        for (int m = 0; m < 4; m++) xv[m] = xnx[m];
    }

    // final fc: partials over own 6 units, reduce across the 4 cohort lanes
    float p0[4], p1[4];
    #pragma unroll
    for (int m = 0; m < 4; m++) { p0[m] = 0.f; p1[m] = 0.f; }
    #pragma unroll
    for (int p = 0; p < 3; p++) {
        const int k = 6 * q + 2 * p;
        const float w00 = __ldg(fc_w + k),      w01 = __ldg(fc_w + k + 1);
        const float w10 = __ldg(fc_w + 24 + k), w11 = __ldg(fc_w + 24 + k + 1);
        #pragma unroll
        for (int m = 0; m < 4; m++) {
            float e0, e1; unpack2(hown[m][p], e0, e1);
            p0[m] += w00 * e0 + w01 * e1;
            p1[m] += w10 * e0 + w11 * e1;
        }
    }
    #pragma unroll
    for (int off = 1; off < 4; off <<= 1) {
        #pragma unroll
        for (int m = 0; m < 4; m++) {
            p0[m] += __shfl_xor_sync(0xFFFFFFFFu, p0[m], off);
            p1[m] += __shfl_xor_sync(0xFFFFFFFFu, p1[m], off);
        }
    }
    if (q == 0) {
        const float fb0 = __ldg(fc_b + 0), fb1 = __ldg(fc_b + 1);
        #pragma unroll
        for (int m = 0; m < 4; m++) {
            out[2 * (sbase + m) + 0] = p0[m] + fb0;
            out[2 * (sbase + m) + 1] = p1[m] + fb1;
        }
    }
}

extern "C" void kernel_launch(void* const* d_in, const int* in_sizes, int n_in,
                              void* d_out, int out_size)
{
    const float* x    = (const float*)d_in[0];
    const float* W_ih = (const float*)d_in[1];
    const float* b_ih = (const float*)d_in[2];
    const float* W_hh = (const float*)d_in[3];
    const float* b_hh = (const float*)d_in[4];
    const float* fc_w = (const float*)d_in[5];
    const float* fc_b = (const float*)d_in[6];
    float* out = (float*)d_out;

    const int B = out_size / 2;
    const int T = in_sizes[0] / B;

    const int grid = B / 32;   // 1 lane per (cohort, quarter); 8 cohorts per CTA
    trendgru_kernel<<<grid, TPB>>>(x, W_ih, b_ih, W_hh, b_hh, fc_w, fc_b, out, B, T);
}

// round 12
// speedup vs baseline: 2.8213x; 1.0013x over previous
#include <cuda_runtime.h>

#define HID 24
#define TPB 32
#define WSTRIDE 218   // u64 stride per q-block (216 payload + 2 pad): q*1744B mod 128 = {0,80,32,112} -> conflict-free

typedef unsigned long long u64;

__device__ __forceinline__ u64 pack2(float x, float y) {
    u64 r; asm("mov.b64 %0, {%1, %2};" : "=l"(r) : "f"(x), "f"(y)); return r;
}
__device__ __forceinline__ void unpack2(u64 v, float &x, float &y) {
    asm("mov.b64 {%0, %1}, %2;" : "=f"(x), "=f"(y) : "l"(v));
}
__device__ __forceinline__ u64 ffma2(u64 a, u64 b, u64 c) {
    u64 d; asm("fma.rn.f32x2 %0, %1, %2, %3;" : "=l"(d) : "l"(a), "l"(b), "l"(c)); return d;
}
__device__ __forceinline__ u64 fadd2(u64 a, u64 b) {
    u64 d; asm("add.rn.f32x2 %0, %1, %2;" : "=l"(d) : "l"(a), "l"(b)); return d;
}
__device__ __forceinline__ float ex2a(float x) {
    float r; asm("ex2.approx.f32 %0, %1;" : "=f"(r) : "f"(x)); return r;
}
__device__ __forceinline__ float rcpa(float x) {
    float r; asm("rcp.approx.f32 %0, %1;" : "=f"(r) : "f"(x)); return r;
}
__device__ __forceinline__ float sig_f(float v) {
    return rcpa(1.0f + ex2a(v * -1.442695041f));
}
__device__ __forceinline__ float tanh_f(float v) {
    return fmaf(2.0f, rcpa(1.0f + ex2a(v * -2.885390082f)), -1.0f);
}

// Cohort = 4 lanes <-> 4 sequences. Lane q owns gate rows {r,z,n} x units
// [6q, 6q+6) and computes FULL k=24 matvec for all 4 cohort seqs (no k-split,
// no reduce). h gathered lazily per k-pair via shfl from the owning lane.
__global__ void __launch_bounds__(TPB, 8)
trendgru_kernel(const float* __restrict__ x,
                const float* __restrict__ W_ih,
                const float* __restrict__ b_ih,
                const float* __restrict__ W_hh,
                const float* __restrict__ b_hh,
                const float* __restrict__ fc_w,
                const float* __restrict__ fc_b,
                float* __restrict__ out,
                int B, int T)
{
    // sW[q*218 + j*24 + k] = pack2(W_hh[r0][k], W_hh[r0+1][k]),
    //  j = gate*3+p (gate 0=r,1=z,2=n), r0 = gate*24 + 6q + 2p, k = 0..23
    __shared__ __align__(16) u64 sW[4 * WSTRIDE];
    __shared__ __align__(16) ulonglong2 cRZ[4][6];  // (W_ih pair, b_ih+b_hh pair)
    __shared__ __align__(16) ulonglong2 cN[4][3];   // (W_ih_n pair, b_ih_n pair)
    __shared__ u64 cNH[4][3];                       // b_hh n pairs

    const int tid = threadIdx.x;
    for (int i = tid; i < 4 * 216; i += TPB) {
        int qq = i / 216, rem = i % 216;
        int j = rem / 24, k = rem % 24;
        int gate = j / 3, p = j % 3;
        int r0 = gate * 24 + 6 * qq + 2 * p;
        sW[qq * WSTRIDE + j * 24 + k] = pack2(W_hh[r0 * HID + k], W_hh[(r0 + 1) * HID + k]);
    }
    if (tid < 24) {
        int qq = tid / 6, j6 = tid % 6;
        int gate = j6 / 3, p = j6 % 3;
        int r0 = gate * 24 + 6 * qq + 2 * p;
        cRZ[qq][j6].x = pack2(W_ih[r0], W_ih[r0 + 1]);
        cRZ[qq][j6].y = pack2(b_ih[r0] + b_hh[r0], b_ih[r0 + 1] + b_hh[r0 + 1]);
    }
    if (tid < 12) {
        int qq = tid / 3, p = tid % 3;
        int r0 = 48 + 6 * qq + 2 * p;
        cN[qq][p].x = pack2(W_ih[r0], W_ih[r0 + 1]);
        cN[qq][p].y = pack2(b_ih[r0], b_ih[r0 + 1]);
        cNH[qq][p]  = pack2(b_hh[r0], b_hh[r0 + 1]);
    }
    __syncthreads();

    const int q    = tid & 3;
    const int cbase = tid & ~3;                    // cohort base lane
    const int sbase = (blockIdx.x * TPB + tid) >> 2 << 2;  // 4 seqs per cohort

    const ulonglong2* wq = reinterpret_cast<const ulonglong2*>(&sW[q * WSTRIDE]);
    const float* xb = x + (size_t)sbase * T;

    u64 hown[4][3];   // own h pairs (units 6q..6q+5) for seqs sbase..sbase+3
    #pragma unroll
    for (int m = 0; m < 4; m++)
        #pragma unroll
        for (int p = 0; p < 3; p++) hown[m][p] = 0ULL;

    const u64 SGN2 = 0x8000000080000000ULL;

    float xv[4];
    #pragma unroll
    for (int m = 0; m < 4; m++) xv[m] = __ldg(xb + (size_t)m * T);

    for (int t = 0; t < T; t++) {
        const int tn = (t + 1 < T) ? (t + 1) : t;
        float xnx[4];
        #pragma unroll
        for (int m = 0; m < 4; m++) xnx[m] = __ldg(xb + (size_t)m * T + tn);

        u64 x2[4];
        #pragma unroll
        for (int m = 0; m < 4; m++) x2[m] = pack2(xv[m], xv[m]);

        u64 acc[4][9];
        #pragma unroll
        for (int j6 = 0; j6 < 6; j6++) {          // r (0-2), z (3-5): fold x-proj + biases
            const ulonglong2 w = cRZ[q][j6];
            #pragma unroll
            for (int m = 0; m < 4; m++)
                acc[m][j6] = ffma2(w.x, x2[m], w.y);
        }
        #pragma unroll
        for (int p = 0; p < 3; p++) {             // hn: start from b_hh
            const u64 bv = cNH[q][p];
            #pragma unroll
            for (int m = 0; m < 4; m++) acc[m][6 + p] = bv;
        }

        // matvec over 12 global h-pairs; pair i owned by lane cbase + i/3
        #pragma unroll
        for (int i = 0; i < 12; i++) {
            const int src = cbase + (i / 3);
            u64 e0[4], e1[4];
            #pragma unroll
            for (int m = 0; m < 4; m++) {
                const u64 hv = __shfl_sync(0xFFFFFFFFu, hown[m][i % 3], src);
                float h0, h1; unpack2(hv, h0, h1);
                e0[m] = pack2(h0, h0);
                e1[m] = pack2(h1, h1);
            }
            #pragma unroll
            for (int j = 0; j < 9; j++) {
                const ulonglong2 w = wq[j * 12 + i];   // k = 2i (x), 2i+1 (y)
                #pragma unroll
                for (int m = 0; m < 4; m++) {
                    acc[m][j] = ffma2(w.x, e0[m], acc[m][j]);
                    acc[m][j] = ffma2(w.y, e1[m], acc[m][j]);
                }
            }
        }

        // gates + h update: own 3 pairs x 4 seqs
        #pragma unroll
        for (int m = 0; m < 4; m++) {
            #pragma unroll
            for (int p = 0; p < 3; p++) {
                float a0, a1, c0, c1;
                unpack2(acc[m][p], a0, a1);
                unpack2(acc[m][3 + p], c0, c1);
                const u64 r2 = pack2(sig_f(a0), sig_f(a1));
                const u64 z2 = pack2(sig_f(c0), sig_f(c1));
                const ulonglong2 wn = cN[q][p];
                const u64 xn = ffma2(wn.x, x2[m], wn.y);
                const u64 npre = ffma2(r2, acc[m][6 + p], xn);
                float n0, n1; unpack2(npre, n0, n1);
                const u64 n2 = pack2(tanh_f(n0), tanh_f(n1));
                // h = n + z*(h - n)
                hown[m][p] = ffma2(z2, fadd2(hown[m][p], n2 ^ SGN2), n2);
            }
        }

        #pragma unroll
        for (int m = 0; m < 4; m++) xv[m] = xnx[m];
    }

    // final fc: partials over own 6 units, reduce across the 4 cohort lanes
    float p0[4], p1[4];
    #pragma unroll
    for (int m = 0; m < 4; m++) { p0[m] = 0.f; p1[m] = 0.f; }
    #pragma unroll
    for (int p = 0; p < 3; p++) {
        const int k = 6 * q + 2 * p;
        const float w00 = __ldg(fc_w + k),      w01 = __ldg(fc_w + k + 1);
        const float w10 = __ldg(fc_w + 24 + k), w11 = __ldg(fc_w + 24 + k + 1);
        #pragma unroll
        for (int m = 0; m < 4; m++) {
            float e0, e1; unpack2(hown[m][p], e0, e1);
            p0[m] += w00 * e0 + w01 * e1;
            p1[m] += w10 * e0 + w11 * e1;
        }
    }
    #pragma unroll
    for (int off = 1; off < 4; off <<= 1) {
        #pragma unroll
        for (int m = 0; m < 4; m++) {
            p0[m] += __shfl_xor_sync(0xFFFFFFFFu, p0[m], off);
            p1[m] += __shfl_xor_sync(0xFFFFFFFFu, p1[m], off);
        }
    }
    if (q == 0) {
        const float fb0 = __ldg(fc_b + 0), fb1 = __ldg(fc_b + 1);
        #pragma unroll
        for (int m = 0; m < 4; m++) {
            out[2 * (sbase + m) + 0] = p0[m] + fb0;
            out[2 * (sbase + m) + 1] = p1[m] + fb1;
        }
    }
}

extern "C" void kernel_launch(void* const* d_in, const int* in_sizes, int n_in,
                              void* d_out, int out_size)
{
    const float* x    = (const float*)d_in[0];
    const float* W_ih = (const float*)d_in[1];
    const float* b_ih = (const float*)d_in[2];
    const float* W_hh = (const float*)d_in[3];
    const float* b_hh = (const float*)d_in[4];
    const float* fc_w = (const float*)d_in[5];
    const float* fc_b = (const float*)d_in[6];
    float* out = (float*)d_out;

    const int B = out_size / 2;
    const int T = in_sizes[0] / B;

    const int grid = B / 32;   // 1 lane per (cohort, quarter); 8 cohorts per CTA
    trendgru_kernel<<<grid, TPB>>>(x, W_ih, b_ih, W_hh, b_hh, fc_w, fc_b, out, B, T);
}